// round 7
// baseline (speedup 1.0000x reference)
#include <cuda_runtime.h>
#include <cuda_bf16.h>
#include <cstdint>

#define D   256
#define KC  1024
#define M_ROWS 65536

// ---- filter smem: enorm table + A tile ----
#define FS_EN   0                  // 1024 floats = 4096 B
#define FS_A    4096               // 128 rows x 260 floats = 133120 B
#define FS_TOTAL 137216

#define WINF 1.5e-3f

__device__ double g_loss_accum;
__device__ int    g_listcnt;
__device__ __align__(16) float g_enorm[KC];
__device__ __align__(16) float g_xn[M_ROWS];
__device__ __align__(16) int4  g_cand[M_ROWS];
__device__ __align__(16) int   g_list[M_ROWS];
// bf16 B fragments: [k16(16)][code(1024)][q(4)] x uint2{ bf16x2(k=2q,2q+1), bf16x2(k=2q+8,2q+9) }
__device__ __align__(16) uint2 g_Bh[16 * 1024 * 4];

__device__ __forceinline__ uint32_t packbf2(float lo, float hi) {
    __nv_bfloat162 h = __floats2bfloat162_rn(lo, hi);   // x (lo) -> low half
    return *(uint32_t*)&h;
}
__device__ __forceinline__ void mma_bf16(float* c, const uint32_t* a, uint32_t b0, uint32_t b1) {
    asm volatile("mma.sync.aligned.m16n8k16.row.col.f32.bf16.bf16.f32 "
                 "{%0,%1,%2,%3}, {%4,%5,%6,%7}, {%8,%9}, {%0,%1,%2,%3};"
                 : "+f"(c[0]), "+f"(c[1]), "+f"(c[2]), "+f"(c[3])
                 : "r"(a[0]), "r"(a[1]), "r"(a[2]), "r"(a[3]), "r"(b0), "r"(b1));
}
// value-then-lowest-index comparator (reference tie-break)
__device__ __forceinline__ bool bt(float va, int ia, float vb, int ib) {
    return va < vb || (va == vb && ia < ib);
}

// ---------------------------------------------------------------------------
// Prep: e-norms (R2-verbatim reduction), bf16 B fragment images, zero accums.
// ---------------------------------------------------------------------------
__global__ void vq_prep(const float* __restrict__ E) {
    int code = blockIdx.x;
    int t = threadIdx.x;          // 64 threads, 4 elems each
    const float4* row = (const float4*)(E + (size_t)code * D);
    float4 v = row[t];
    float s = v.x * v.x + v.y * v.y + v.z * v.z + v.w * v.w;
    #pragma unroll
    for (int o = 16; o > 0; o >>= 1) s += __shfl_xor_sync(0xFFFFFFFFu, s, o);
    __shared__ float ws[2];
    if ((t & 31) == 0) ws[t >> 5] = s;
    __syncthreads();
    if (t == 0) {
        g_enorm[code] = ws[0] + ws[1];
        if (code == 0) { g_loss_accum = 0.0; g_listcnt = 0; }
    }

    // bf16 pairs into fragment image. Thread t owns k = 4t..4t+3 -> pairs 2t, 2t+1.
    uint32_t* W = (uint32_t*)g_Bh;
    float f[4] = {v.x, v.y, v.z, v.w};
    #pragma unroll
    for (int pp = 0; pp < 2; pp++) {
        int p = 2 * t + pp;              // pair index (k = 2p, 2p+1)
        int k16 = p >> 3, r = p & 7, h = r >> 2, q = r & 3;
        uint32_t w = packbf2(f[pp * 2], f[pp * 2 + 1]);
        W[(((size_t)k16 * 1024 + code) * 4 + q) * 2 + h] = w;
    }
}

// ---------------------------------------------------------------------------
// xnorm: R2's per-row ||x||^2, verbatim structure.
// ---------------------------------------------------------------------------
__global__ void vq_xnorm(const float* __restrict__ X) {
    int tid = threadIdx.x;
    int row0 = blockIdx.x * 128;
    int r = tid >> 1, h = tid & 1;
    const float4* xr = (const float4*)(X + (size_t)(row0 + r) * D + h * 128);
    float s = 0.f;
    #pragma unroll
    for (int j = 0; j < 32; j++) {
        float4 v = xr[j];
        s += v.x * v.x + v.y * v.y + v.z * v.z + v.w * v.w;
    }
    s += __shfl_xor_sync(0xFFFFFFFFu, s, 1);
    if (h == 0) g_xn[row0 + r] = s;
}

// ---------------------------------------------------------------------------
// Filter: bf16 m16n8k16 warp-MMA, B frags via coalesced L1 LDG, no in-loop
// barriers. Top-3 candidates per row + fallback flag.
// ---------------------------------------------------------------------------
__global__ void __launch_bounds__(256, 1)
vq_filter(const float* __restrict__ X) {
    extern __shared__ char sm[];
    const int tid  = threadIdx.x;
    const int lane = tid & 31;
    const int warp = tid >> 5;
    const int row0 = blockIdx.x * 128;

    float* s_en = (float*)(sm + FS_EN);
    float* As   = (float*)(sm + FS_A);

    // A tile into smem (row stride 260)
    for (int i = tid; i < 128 * 64; i += 256) {
        int r = i >> 6, c4 = i & 63;
        float4 v = *(const float4*)(X + (size_t)(row0 + r) * D + c4 * 4);
        *(float4*)(As + r * 260 + c4 * 4) = v;
    }
    for (int i = tid; i < KC; i += 256) s_en[i] = g_enorm[i];
    __syncthreads();

    const int rA = warp * 16 + (lane >> 2);
    const float* pA0 = As + rA * 260;
    const float* pA1 = pA0 + 8 * 260;
    const int laneK = (lane & 3) * 2;

    float v1[2] = {3e38f, 3e38f}, v2[2] = {3e38f, 3e38f}, v3[2] = {3e38f, 3e38f};
    int   i1[2] = {0, 0},         i2[2] = {0, 0},         i3[2] = {0, 0};

    #define INS3(slot, sv, sidx) do { \
        float _s = (sv); int _i = (sidx); \
        if (_s < v3[slot]) { \
            if (_s < v2[slot]) { \
                v3[slot] = v2[slot]; i3[slot] = i2[slot]; \
                if (_s < v1[slot]) { v2[slot] = v1[slot]; i2[slot] = i1[slot]; \
                                     v1[slot] = _s; i1[slot] = _i; } \
                else               { v2[slot] = _s; i2[slot] = _i; } \
            } else { v3[slot] = _s; i3[slot] = _i; } \
        } } while (0)

    for (int nc = 0; nc < 8; nc++) {
        float C[16][4];
        #pragma unroll
        for (int nt = 0; nt < 16; nt++)
            #pragma unroll
            for (int j = 0; j < 4; j++) C[nt][j] = 0.f;

        #pragma unroll
        for (int k16 = 0; k16 < 16; k16++) {
            int kg = k16 * 16 + laneK;
            float2 x0 = *(const float2*)(pA0 + kg);
            float2 x1 = *(const float2*)(pA1 + kg);
            float2 x2 = *(const float2*)(pA0 + kg + 8);
            float2 x3 = *(const float2*)(pA1 + kg + 8);
            uint32_t a[4];
            a[0] = packbf2(x0.x, x0.y);
            a[1] = packbf2(x1.x, x1.y);
            a[2] = packbf2(x2.x, x2.y);
            a[3] = packbf2(x3.x, x3.y);
            const uint2* pb = g_Bh + ((size_t)k16 * 1024 + nc * 128 + (lane >> 2)) * 4
                            + (lane & 3);
            #pragma unroll
            for (int nt = 0; nt < 16; nt++) {
                uint2 b = __ldg(pb + nt * 32);
                mma_bf16(C[nt], a, b.x, b.y);
            }
        }

        // epilogue: approx score = en - 2*dot (xn-free ranking), insert top-3
        #pragma unroll
        for (int nt = 0; nt < 16; nt++) {
            int cl = nt * 8 + laneK;
            int col0 = nc * 128 + cl;
            float en0 = s_en[col0], en1 = s_en[col0 + 1];
            INS3(0, __fmaf_rn(-2.f, C[nt][0], en0), col0);
            INS3(0, __fmaf_rn(-2.f, C[nt][1], en1), col0 + 1);
            INS3(1, __fmaf_rn(-2.f, C[nt][2], en0), col0);
            INS3(1, __fmaf_rn(-2.f, C[nt][3], en1), col0 + 1);
        }
    }

    // quad merge (lanes sharing rows)
    #pragma unroll
    for (int o = 1; o < 4; o <<= 1) {
        #pragma unroll
        for (int sl = 0; sl < 2; sl++) {
            float tv[3]; int ti[3];
            tv[0] = __shfl_xor_sync(0xFFFFFFFFu, v1[sl], o);
            ti[0] = __shfl_xor_sync(0xFFFFFFFFu, i1[sl], o);
            tv[1] = __shfl_xor_sync(0xFFFFFFFFu, v2[sl], o);
            ti[1] = __shfl_xor_sync(0xFFFFFFFFu, i2[sl], o);
            tv[2] = __shfl_xor_sync(0xFFFFFFFFu, v3[sl], o);
            ti[2] = __shfl_xor_sync(0xFFFFFFFFu, i3[sl], o);
            float mv[3] = {v1[sl], v2[sl], v3[sl]};
            int   mi[3] = {i1[sl], i2[sl], i3[sl]};
            float rv[3]; int ri[3];
            int a = 0, b = 0;
            #pragma unroll
            for (int k = 0; k < 3; k++) {
                bool ta = (b >= 3) || (a < 3 && bt(mv[a], mi[a], tv[b], ti[b]));
                rv[k] = ta ? mv[a] : tv[b];
                ri[k] = ta ? mi[a] : ti[b];
                if (ta) a++; else b++;
            }
            v1[sl] = rv[0]; i1[sl] = ri[0];
            v2[sl] = rv[1]; i2[sl] = ri[1];
            v3[sl] = rv[2]; i3[sl] = ri[2];
        }
    }

    if ((lane & 3) == 0) {
        int f0 = (v3[0] < v1[0] + WINF) ? 1 : 0;
        int f1 = (v3[1] < v1[1] + WINF) ? 1 : 0;
        g_cand[row0 + rA]     = make_int4(i1[0], i2[0], i3[0], f0);
        g_cand[row0 + rA + 8] = make_int4(i1[1], i2[1], i3[1], f1);
    }
}

// ---------------------------------------------------------------------------
// Refine: thread-per-candidate exact chains. 64 rows x 4 threads per block.
// ---------------------------------------------------------------------------
#define RX_STRIDE 264
__global__ void __launch_bounds__(256)
vq_refine(const float* __restrict__ X, const float* __restrict__ E,
          float* __restrict__ out) {
    extern __shared__ float sxr[];         // 64 rows x 264 floats
    __shared__ int   s_bi[64];
    __shared__ float s_lv[64];
    const int tid = threadIdx.x;
    const int r   = tid >> 2;              // row within block
    const int j   = tid & 3;               // candidate slot
    const int row0 = blockIdx.x * 64;
    const int row  = row0 + r;

    for (int i = tid; i < 64 * 64; i += 256) {
        int rr = i >> 6, c4 = i & 63;
        float4 v = *(const float4*)(X + (size_t)(row0 + rr) * D + c4 * 4);
        *(float4*)(sxr + rr * RX_STRIDE + c4 * 4) = v;
    }
    __syncthreads();

    const int4 cd = g_cand[row];
    float bv = 3e38f; int bn = 0x7FFFFFFF;

    if (cd.w) {
        if (j == 0) {
            int slot = atomicAdd(&g_listcnt, 1);
            g_list[slot] = row;
        }
    } else {
        const float xn = g_xn[row];
        int c = (j == 0) ? cd.x : (j == 1) ? cd.y : (j == 2) ? cd.z : cd.x;
        const float*  xr = sxr + r * RX_STRIDE;
        const float4* ee = (const float4*)(E + (size_t)c * D);
        float d = 0.f;
        #pragma unroll 8
        for (int k4 = 0; k4 < 64; k4++) {
            float4 e  = __ldg(&ee[k4]);
            float4 xv = *(const float4*)(xr + k4 * 4);
            d = __fmaf_rn(xv.x, e.x, d);
            d = __fmaf_rn(xv.y, e.y, d);
            d = __fmaf_rn(xv.z, e.z, d);
            d = __fmaf_rn(xv.w, e.w, d);
        }
        bv = __fmaf_rn(-2.f, d, __fadd_rn(xn, __ldg(&g_enorm[c])));
        bn = c;
    }

    // group-of-4 argmin (lowest-index ties)
    #pragma unroll
    for (int o = 1; o < 4; o <<= 1) {
        float ov = __shfl_xor_sync(0xFFFFFFFFu, bv, o);
        int   on = __shfl_xor_sync(0xFFFFFFFFu, bn, o);
        if (bt(ov, on, bv, bn)) { bv = ov; bn = on; }
    }
    if (j == 0) {
        s_bi[r] = cd.w ? -1 : bn;
        s_lv[r] = cd.w ? 0.f : bv;
    }
    __syncthreads();

    // loss partial
    if (tid < 64) {
        float l = s_lv[tid];
        #pragma unroll
        for (int o = 16; o > 0; o >>= 1) l += __shfl_xor_sync(0xFFFFFFFFu, l, o);
        if ((tid & 31) == 0) atomicAdd(&g_loss_accum, (double)l);
    }

    // STE output: out = fl(x + fl(q - x)); flagged rows handled by fullscan
    for (int u = tid; u < 64 * 64; u += 256) {
        int m = u >> 6, c4 = u & 63;
        int code = s_bi[m];
        if (code < 0) continue;
        float4 q = __ldg((const float4*)(E + (size_t)code * D + c4 * 4));
        float4 x = *(const float4*)(sxr + m * RX_STRIDE + c4 * 4);
        float4 rr;
        rr.x = __fadd_rn(x.x, __fsub_rn(q.x, x.x));
        rr.y = __fadd_rn(x.y, __fsub_rn(q.y, x.y));
        rr.z = __fadd_rn(x.z, __fsub_rn(q.z, x.z));
        rr.w = __fadd_rn(x.w, __fsub_rn(q.w, x.w));
        *(float4*)(out + (size_t)(row0 + m) * D + c4 * 4) = rr;
    }
}

// ---------------------------------------------------------------------------
// Fullscan: block-per-flagged-row, all 1024 codes, exact chains (ILP-4).
// ---------------------------------------------------------------------------
__global__ void __launch_bounds__(256)
vq_fullscan(const float* __restrict__ X, const float* __restrict__ E,
            float* __restrict__ out) {
    __shared__ float sx[256];
    __shared__ float s_wv[8];
    __shared__ int   s_wn[8];
    __shared__ int   s_code;
    const int tid  = threadIdx.x;
    const int lane = tid & 31;
    const int warp = tid >> 5;
    const int n = g_listcnt;

    for (int i = blockIdx.x; i < n; i += gridDim.x) {
        const int row = g_list[i];
        sx[tid] = X[(size_t)row * D + tid];
        __syncthreads();
        const float xn = g_xn[row];

        int c = tid;
        float d0 = 0.f, d1 = 0.f, d2 = 0.f, d3 = 0.f;
        const float* e0 = E + (size_t)(c)       * D;
        const float* e1 = E + (size_t)(c + 256) * D;
        const float* e2 = E + (size_t)(c + 512) * D;
        const float* e3 = E + (size_t)(c + 768) * D;
        #pragma unroll 8
        for (int k = 0; k < 256; k++) {
            float xv = sx[k];
            d0 = __fmaf_rn(xv, __ldg(&e0[k]), d0);
            d1 = __fmaf_rn(xv, __ldg(&e1[k]), d1);
            d2 = __fmaf_rn(xv, __ldg(&e2[k]), d2);
            d3 = __fmaf_rn(xv, __ldg(&e3[k]), d3);
        }
        float bv = 3e38f; int bn = 0;
        float s;
        s = __fmaf_rn(-2.f, d0, __fadd_rn(xn, __ldg(&g_enorm[c])));
        bv = s; bn = c;
        s = __fmaf_rn(-2.f, d1, __fadd_rn(xn, __ldg(&g_enorm[c + 256])));
        if (bt(s, c + 256, bv, bn)) { bv = s; bn = c + 256; }
        s = __fmaf_rn(-2.f, d2, __fadd_rn(xn, __ldg(&g_enorm[c + 512])));
        if (bt(s, c + 512, bv, bn)) { bv = s; bn = c + 512; }
        s = __fmaf_rn(-2.f, d3, __fadd_rn(xn, __ldg(&g_enorm[c + 768])));
        if (bt(s, c + 768, bv, bn)) { bv = s; bn = c + 768; }

        #pragma unroll
        for (int o = 16; o > 0; o >>= 1) {
            float ov = __shfl_xor_sync(0xFFFFFFFFu, bv, o);
            int   on = __shfl_xor_sync(0xFFFFFFFFu, bn, o);
            if (bt(ov, on, bv, bn)) { bv = ov; bn = on; }
        }
        if (lane == 0) { s_wv[warp] = bv; s_wn[warp] = bn; }
        __syncthreads();
        if (tid == 0) {
            float fv = s_wv[0]; int fn = s_wn[0];
            #pragma unroll
            for (int w = 1; w < 8; w++)
                if (bt(s_wv[w], s_wn[w], fv, fn)) { fv = s_wv[w]; fn = s_wn[w]; }
            s_code = fn;
            atomicAdd(&g_loss_accum, (double)fv);
        }
        __syncthreads();

        int code = s_code;
        float q = __ldg(&E[(size_t)code * D + tid]);
        float x = sx[tid];
        out[(size_t)row * D + tid] = __fadd_rn(x, __fsub_rn(q, x));
        __syncthreads();
    }
}

__global__ void vq_finish(float* __restrict__ out, int total_elems) {
    out[total_elems] = (float)(1.25 * g_loss_accum / (double)total_elems);
}

extern "C" void kernel_launch(void* const* d_in, const int* in_sizes, int n_in,
                              void* d_out, int out_size) {
    const float* X = (const float*)d_in[0];   // latents  [8192, 2048] fp32
    const float* E = (const float*)d_in[1];   // embedding [1024, 256] fp32
    float* out = (float*)d_out;
    int M = in_sizes[0] / D;                  // 65536 rows

    cudaFuncSetAttribute(vq_filter, cudaFuncAttributeMaxDynamicSharedMemorySize, FS_TOTAL);
    cudaFuncSetAttribute(vq_refine, cudaFuncAttributeMaxDynamicSharedMemorySize,
                         64 * RX_STRIDE * 4);
    vq_prep<<<KC, 64>>>(E);
    vq_xnorm<<<M / 128, 256>>>(X);
    vq_filter<<<M / 128, 256, FS_TOTAL>>>(X);
    vq_refine<<<M / 64, 256, 64 * RX_STRIDE * 4>>>(X, E, out);
    vq_fullscan<<<128, 256>>>(X, E, out);
    vq_finish<<<1, 1>>>(out, out_size - 1);
}

// round 8
// speedup vs baseline: 8.2598x; 8.2598x over previous
#include <cuda_runtime.h>
#include <cstdint>

#define D   256
#define KC  1024
#define M_ROWS 65536

// ---- filter smem: enorm table + A tile ----
#define FS_EN   0                  // 1024 floats = 4096 B
#define FS_A    4096               // 128 rows x 260 floats = 133120 B
#define FS_TOTAL 137216

#define WINF 1.5e-4f

__device__ double g_loss_accum;
__device__ int    g_listcnt;
__device__ __align__(16) float g_enorm[KC];
__device__ __align__(16) float g_xn[M_ROWS];
__device__ __align__(16) int4  g_cand[M_ROWS];
__device__ __align__(16) int   g_list[M_ROWS];
// tf32 B fragments: [k8p(16)][code(1024)][t(4)] x uint4
//   { B[k8p*8+t], B[k8p*8+t+4], B[128+k8p*8+t], B[128+k8p*8+t+4] }
__device__ __align__(16) uint4 g_Bt[16 * 1024 * 4];

__device__ __forceinline__ uint32_t f2tf32(float x) {
    uint32_t r; asm("cvt.rna.tf32.f32 %0, %1;" : "=r"(r) : "f"(x)); return r;
}
__device__ __forceinline__ void mma_tf32(float* c, const uint32_t* a, uint32_t b0, uint32_t b1) {
    asm volatile("mma.sync.aligned.m16n8k8.row.col.f32.tf32.tf32.f32 "
                 "{%0,%1,%2,%3}, {%4,%5,%6,%7}, {%8,%9}, {%0,%1,%2,%3};"
                 : "+f"(c[0]), "+f"(c[1]), "+f"(c[2]), "+f"(c[3])
                 : "r"(a[0]), "r"(a[1]), "r"(a[2]), "r"(a[3]), "r"(b0), "r"(b1));
}
// value-then-lowest-index comparator (reference tie-break)
__device__ __forceinline__ bool bt(float va, int ia, float vb, int ib) {
    return va < vb || (va == vb && ia < ib);
}

// ---------------------------------------------------------------------------
// Prep: e-norms (R2-verbatim reduction), tf32 B fragment images, zero accums.
// ---------------------------------------------------------------------------
__global__ void vq_prep(const float* __restrict__ E) {
    int code = blockIdx.x;
    int t = threadIdx.x;          // 64 threads, 4 elems each
    const float4* row = (const float4*)(E + (size_t)code * D);
    float4 v = row[t];
    float s = v.x * v.x + v.y * v.y + v.z * v.z + v.w * v.w;
    #pragma unroll
    for (int o = 16; o > 0; o >>= 1) s += __shfl_xor_sync(0xFFFFFFFFu, s, o);
    __shared__ float ws[2];
    if ((t & 31) == 0) ws[t >> 5] = s;
    __syncthreads();
    if (t == 0) {
        g_enorm[code] = ws[0] + ws[1];
        if (code == 0) { g_loss_accum = 0.0; g_listcnt = 0; }
    }

    // tf32 scalars into fragment image
    float* Wt = (float*)g_Bt;
    float f[4] = {v.x, v.y, v.z, v.w};
    #pragma unroll
    for (int e = 0; e < 4; e++) {
        int k   = t * 4 + e;
        int k8  = k >> 3;
        int k8p = k8 & 15, hi = k8 >> 4;
        int rem = k & 7;
        int comp = 2 * hi + (rem >> 2);
        int tq   = rem & 3;
        uint32_t w = f2tf32(f[e]);
        Wt[(((size_t)k8p * 1024 + code) * 4 + tq) * 4 + comp] = __uint_as_float(w);
    }
}

// ---------------------------------------------------------------------------
// xnorm: R2's per-row ||x||^2, verbatim structure.
// ---------------------------------------------------------------------------
__global__ void vq_xnorm(const float* __restrict__ X) {
    int tid = threadIdx.x;
    int row0 = blockIdx.x * 128;
    int r = tid >> 1, h = tid & 1;
    const float4* xr = (const float4*)(X + (size_t)(row0 + r) * D + h * 128);
    float s = 0.f;
    #pragma unroll
    for (int j = 0; j < 32; j++) {
        float4 v = xr[j];
        s += v.x * v.x + v.y * v.y + v.z * v.z + v.w * v.w;
    }
    s += __shfl_xor_sync(0xFFFFFFFFu, s, 1);
    if (h == 0) g_xn[row0 + r] = s;
}

// ---------------------------------------------------------------------------
// Filter: tf32 m16n8k8 warp-MMA (single pass, R5-validated numerics), B frags
// via coalesced LDG.128 (one load feeds two MMAs), no in-loop barriers.
// Top-3 candidates per row + fallback flag.
// ---------------------------------------------------------------------------
__global__ void __launch_bounds__(256, 1)
vq_filter(const float* __restrict__ X) {
    extern __shared__ char sm[];
    const int tid  = threadIdx.x;
    const int lane = tid & 31;
    const int warp = tid >> 5;
    const int row0 = blockIdx.x * 128;

    float* s_en = (float*)(sm + FS_EN);
    float* As   = (float*)(sm + FS_A);

    // A tile into smem (row stride 260)
    for (int i = tid; i < 128 * 64; i += 256) {
        int r = i >> 6, c4 = i & 63;
        float4 v = *(const float4*)(X + (size_t)(row0 + r) * D + c4 * 4);
        *(float4*)(As + r * 260 + c4 * 4) = v;
    }
    for (int i = tid; i < KC; i += 256) s_en[i] = g_enorm[i];
    __syncthreads();

    const int rA = warp * 16 + (lane >> 2);
    const float* pA0 = As + rA * 260 + (lane & 3);
    const float* pA1 = pA0 + 8 * 260;

    float v1[2] = {3e38f, 3e38f}, v2[2] = {3e38f, 3e38f}, v3[2] = {3e38f, 3e38f};
    int   i1[2] = {0, 0},         i2[2] = {0, 0},         i3[2] = {0, 0};

    #define INS3(slot, sv, sidx) do { \
        float _s = (sv); int _i = (sidx); \
        if (_s < v3[slot]) { \
            if (_s < v2[slot]) { \
                v3[slot] = v2[slot]; i3[slot] = i2[slot]; \
                if (_s < v1[slot]) { v2[slot] = v1[slot]; i2[slot] = i1[slot]; \
                                     v1[slot] = _s; i1[slot] = _i; } \
                else               { v2[slot] = _s; i2[slot] = _i; } \
            } else { v3[slot] = _s; i3[slot] = _i; } \
        } } while (0)

    for (int nc = 0; nc < 8; nc++) {
        float C[16][4];
        #pragma unroll
        for (int nt = 0; nt < 16; nt++)
            #pragma unroll
            for (int j = 0; j < 4; j++) C[nt][j] = 0.f;

        #pragma unroll
        for (int k8p = 0; k8p < 16; k8p++) {
            int kg1 = k8p * 8;
            int kg2 = 128 + kg1;
            uint32_t alo[4], ahi[4];
            alo[0] = f2tf32(pA0[kg1]);
            alo[1] = f2tf32(pA1[kg1]);
            alo[2] = f2tf32(pA0[kg1 + 4]);
            alo[3] = f2tf32(pA1[kg1 + 4]);
            ahi[0] = f2tf32(pA0[kg2]);
            ahi[1] = f2tf32(pA1[kg2]);
            ahi[2] = f2tf32(pA0[kg2 + 4]);
            ahi[3] = f2tf32(pA1[kg2 + 4]);
            const uint4* pb = g_Bt + ((size_t)k8p * 1024 + nc * 128 + (lane >> 2)) * 4
                            + (lane & 3);
            #pragma unroll
            for (int nt = 0; nt < 16; nt++) {
                uint4 b = __ldg(pb + nt * 32);
                mma_tf32(C[nt], alo, b.x, b.y);
                mma_tf32(C[nt], ahi, b.z, b.w);
            }
        }

        // epilogue: approx score = en - 2*dot (xn-free ranking), insert top-3
        #pragma unroll
        for (int nt = 0; nt < 16; nt++) {
            int cl = nt * 8 + (lane & 3) * 2;
            int col0 = nc * 128 + cl;
            float en0 = s_en[col0], en1 = s_en[col0 + 1];
            INS3(0, __fmaf_rn(-2.f, C[nt][0], en0), col0);
            INS3(0, __fmaf_rn(-2.f, C[nt][1], en1), col0 + 1);
            INS3(1, __fmaf_rn(-2.f, C[nt][2], en0), col0);
            INS3(1, __fmaf_rn(-2.f, C[nt][3], en1), col0 + 1);
        }
    }

    // quad merge (lanes sharing rows)
    #pragma unroll
    for (int o = 1; o < 4; o <<= 1) {
        #pragma unroll
        for (int sl = 0; sl < 2; sl++) {
            float tv[3]; int ti[3];
            tv[0] = __shfl_xor_sync(0xFFFFFFFFu, v1[sl], o);
            ti[0] = __shfl_xor_sync(0xFFFFFFFFu, i1[sl], o);
            tv[1] = __shfl_xor_sync(0xFFFFFFFFu, v2[sl], o);
            ti[1] = __shfl_xor_sync(0xFFFFFFFFu, i2[sl], o);
            tv[2] = __shfl_xor_sync(0xFFFFFFFFu, v3[sl], o);
            ti[2] = __shfl_xor_sync(0xFFFFFFFFu, i3[sl], o);
            float mv[3] = {v1[sl], v2[sl], v3[sl]};
            int   mi[3] = {i1[sl], i2[sl], i3[sl]};
            float rv[3]; int ri[3];
            int a = 0, b = 0;
            #pragma unroll
            for (int k = 0; k < 3; k++) {
                bool ta = (b >= 3) || (a < 3 && bt(mv[a], mi[a], tv[b], ti[b]));
                rv[k] = ta ? mv[a] : tv[b];
                ri[k] = ta ? mi[a] : ti[b];
                if (ta) a++; else b++;
            }
            v1[sl] = rv[0]; i1[sl] = ri[0];
            v2[sl] = rv[1]; i2[sl] = ri[1];
            v3[sl] = rv[2]; i3[sl] = ri[2];
        }
    }

    if ((lane & 3) == 0) {
        int f0 = (v3[0] < v1[0] + WINF) ? 1 : 0;
        int f1 = (v3[1] < v1[1] + WINF) ? 1 : 0;
        g_cand[row0 + rA]     = make_int4(i1[0], i2[0], i3[0], f0);
        g_cand[row0 + rA + 8] = make_int4(i1[1], i2[1], i3[1], f1);
    }
}

// ---------------------------------------------------------------------------
// Refine: thread-per-candidate exact chains. 64 rows x 4 threads per block.
// ---------------------------------------------------------------------------
#define RX_STRIDE 264
__global__ void __launch_bounds__(256)
vq_refine(const float* __restrict__ X, const float* __restrict__ E,
          float* __restrict__ out) {
    extern __shared__ float sxr[];         // 64 rows x 264 floats
    __shared__ int   s_bi[64];
    __shared__ float s_lv[64];
    const int tid = threadIdx.x;
    const int r   = tid >> 2;              // row within block
    const int j   = tid & 3;               // candidate slot
    const int row0 = blockIdx.x * 64;
    const int row  = row0 + r;

    for (int i = tid; i < 64 * 64; i += 256) {
        int rr = i >> 6, c4 = i & 63;
        float4 v = *(const float4*)(X + (size_t)(row0 + rr) * D + c4 * 4);
        *(float4*)(sxr + rr * RX_STRIDE + c4 * 4) = v;
    }
    __syncthreads();

    const int4 cd = g_cand[row];
    float bv = 3e38f; int bn = 0x7FFFFFFF;

    if (cd.w) {
        if (j == 0) {
            int slot = atomicAdd(&g_listcnt, 1);
            g_list[slot] = row;
        }
    } else {
        const float xn = g_xn[row];
        int c = (j == 0) ? cd.x : (j == 1) ? cd.y : (j == 2) ? cd.z : cd.x;
        const float*  xr = sxr + r * RX_STRIDE;
        const float4* ee = (const float4*)(E + (size_t)c * D);
        float d = 0.f;
        #pragma unroll 8
        for (int k4 = 0; k4 < 64; k4++) {
            float4 e  = __ldg(&ee[k4]);
            float4 xv = *(const float4*)(xr + k4 * 4);
            d = __fmaf_rn(xv.x, e.x, d);
            d = __fmaf_rn(xv.y, e.y, d);
            d = __fmaf_rn(xv.z, e.z, d);
            d = __fmaf_rn(xv.w, e.w, d);
        }
        bv = __fmaf_rn(-2.f, d, __fadd_rn(xn, __ldg(&g_enorm[c])));
        bn = c;
    }

    // group-of-4 argmin (lowest-index ties)
    #pragma unroll
    for (int o = 1; o < 4; o <<= 1) {
        float ov = __shfl_xor_sync(0xFFFFFFFFu, bv, o);
        int   on = __shfl_xor_sync(0xFFFFFFFFu, bn, o);
        if (bt(ov, on, bv, bn)) { bv = ov; bn = on; }
    }
    if (j == 0) {
        s_bi[r] = cd.w ? -1 : bn;
        s_lv[r] = cd.w ? 0.f : bv;
    }
    __syncthreads();

    // loss partial
    if (tid < 64) {
        float l = s_lv[tid];
        #pragma unroll
        for (int o = 16; o > 0; o >>= 1) l += __shfl_xor_sync(0xFFFFFFFFu, l, o);
        if ((tid & 31) == 0) atomicAdd(&g_loss_accum, (double)l);
    }

    // STE output: out = fl(x + fl(q - x)); flagged rows handled by fullscan
    for (int u = tid; u < 64 * 64; u += 256) {
        int m = u >> 6, c4 = u & 63;
        int code = s_bi[m];
        if (code < 0) continue;
        float4 q = __ldg((const float4*)(E + (size_t)code * D + c4 * 4));
        float4 x = *(const float4*)(sxr + m * RX_STRIDE + c4 * 4);
        float4 rr;
        rr.x = __fadd_rn(x.x, __fsub_rn(q.x, x.x));
        rr.y = __fadd_rn(x.y, __fsub_rn(q.y, x.y));
        rr.z = __fadd_rn(x.z, __fsub_rn(q.z, x.z));
        rr.w = __fadd_rn(x.w, __fsub_rn(q.w, x.w));
        *(float4*)(out + (size_t)(row0 + m) * D + c4 * 4) = rr;
    }
}

// ---------------------------------------------------------------------------
// Fullscan: block-per-flagged-row, all 1024 codes, exact float4 chains (ILP-4).
// ---------------------------------------------------------------------------
__global__ void __launch_bounds__(256)
vq_fullscan(const float* __restrict__ X, const float* __restrict__ E,
            float* __restrict__ out) {
    __shared__ float sx[256];
    __shared__ float s_wv[8];
    __shared__ int   s_wn[8];
    __shared__ int   s_code;
    const int tid  = threadIdx.x;
    const int lane = tid & 31;
    const int warp = tid >> 5;
    const int n = g_listcnt;

    for (int i = blockIdx.x; i < n; i += gridDim.x) {
        const int row = g_list[i];
        sx[tid] = X[(size_t)row * D + tid];
        __syncthreads();
        const float xn = g_xn[row];

        int c = tid;
        float d0 = 0.f, d1 = 0.f, d2 = 0.f, d3 = 0.f;
        const float4* e0 = (const float4*)(E + (size_t)(c)       * D);
        const float4* e1 = (const float4*)(E + (size_t)(c + 256) * D);
        const float4* e2 = (const float4*)(E + (size_t)(c + 512) * D);
        const float4* e3 = (const float4*)(E + (size_t)(c + 768) * D);
        #pragma unroll 4
        for (int k4 = 0; k4 < 64; k4++) {
            float4 xv = *(const float4*)(sx + k4 * 4);
            float4 a = __ldg(&e0[k4]);
            d0 = __fmaf_rn(xv.x, a.x, d0); d0 = __fmaf_rn(xv.y, a.y, d0);
            d0 = __fmaf_rn(xv.z, a.z, d0); d0 = __fmaf_rn(xv.w, a.w, d0);
            float4 b = __ldg(&e1[k4]);
            d1 = __fmaf_rn(xv.x, b.x, d1); d1 = __fmaf_rn(xv.y, b.y, d1);
            d1 = __fmaf_rn(xv.z, b.z, d1); d1 = __fmaf_rn(xv.w, b.w, d1);
            float4 cc = __ldg(&e2[k4]);
            d2 = __fmaf_rn(xv.x, cc.x, d2); d2 = __fmaf_rn(xv.y, cc.y, d2);
            d2 = __fmaf_rn(xv.z, cc.z, d2); d2 = __fmaf_rn(xv.w, cc.w, d2);
            float4 dd = __ldg(&e3[k4]);
            d3 = __fmaf_rn(xv.x, dd.x, d3); d3 = __fmaf_rn(xv.y, dd.y, d3);
            d3 = __fmaf_rn(xv.z, dd.z, d3); d3 = __fmaf_rn(xv.w, dd.w, d3);
        }
        float bv; int bn;
        float s;
        s = __fmaf_rn(-2.f, d0, __fadd_rn(xn, __ldg(&g_enorm[c])));
        bv = s; bn = c;
        s = __fmaf_rn(-2.f, d1, __fadd_rn(xn, __ldg(&g_enorm[c + 256])));
        if (bt(s, c + 256, bv, bn)) { bv = s; bn = c + 256; }
        s = __fmaf_rn(-2.f, d2, __fadd_rn(xn, __ldg(&g_enorm[c + 512])));
        if (bt(s, c + 512, bv, bn)) { bv = s; bn = c + 512; }
        s = __fmaf_rn(-2.f, d3, __fadd_rn(xn, __ldg(&g_enorm[c + 768])));
        if (bt(s, c + 768, bv, bn)) { bv = s; bn = c + 768; }

        #pragma unroll
        for (int o = 16; o > 0; o >>= 1) {
            float ov = __shfl_xor_sync(0xFFFFFFFFu, bv, o);
            int   on = __shfl_xor_sync(0xFFFFFFFFu, bn, o);
            if (bt(ov, on, bv, bn)) { bv = ov; bn = on; }
        }
        if (lane == 0) { s_wv[warp] = bv; s_wn[warp] = bn; }
        __syncthreads();
        if (tid == 0) {
            float fv = s_wv[0]; int fn = s_wn[0];
            #pragma unroll
            for (int w = 1; w < 8; w++)
                if (bt(s_wv[w], s_wn[w], fv, fn)) { fv = s_wv[w]; fn = s_wn[w]; }
            s_code = fn;
            atomicAdd(&g_loss_accum, (double)fv);
        }
        __syncthreads();

        int code = s_code;
        float q = __ldg(&E[(size_t)code * D + tid]);
        float x = sx[tid];
        out[(size_t)row * D + tid] = __fadd_rn(x, __fsub_rn(q, x));
        __syncthreads();
    }
}

__global__ void vq_finish(float* __restrict__ out, int total_elems) {
    out[total_elems] = (float)(1.25 * g_loss_accum / (double)total_elems);
}

extern "C" void kernel_launch(void* const* d_in, const int* in_sizes, int n_in,
                              void* d_out, int out_size) {
    const float* X = (const float*)d_in[0];   // latents  [8192, 2048] fp32
    const float* E = (const float*)d_in[1];   // embedding [1024, 256] fp32
    float* out = (float*)d_out;
    int M = in_sizes[0] / D;                  // 65536 rows

    cudaFuncSetAttribute(vq_filter, cudaFuncAttributeMaxDynamicSharedMemorySize, FS_TOTAL);
    cudaFuncSetAttribute(vq_refine, cudaFuncAttributeMaxDynamicSharedMemorySize,
                         64 * RX_STRIDE * 4);
    vq_prep<<<KC, 64>>>(E);
    vq_xnorm<<<M / 128, 256>>>(X);
    vq_filter<<<M / 128, 256, FS_TOTAL>>>(X);
    vq_refine<<<M / 64, 256, 64 * RX_STRIDE * 4>>>(X, E, out);
    vq_fullscan<<<256, 256>>>(X, E, out);
    vq_finish<<<1, 1>>>(out, out_size - 1);
}

// round 9
// speedup vs baseline: 11.9737x; 1.4496x over previous
#include <cuda_runtime.h>
#include <cuda_fp16.h>
#include <cstdint>

#define D   256
#define KC  1024
#define M_ROWS 65536

// ---- filter smem: enorm table + fp16 A tile ----
#define FS_EN   0                  // 1024 floats = 4096 B
#define FS_A    4096               // 128 rows x 264 fp16 = 67584 B
#define FS_TOTAL 71680
#define AW_STRIDE 132              // uint32 words per A row (264 fp16 / 2)

#define WINF 2.5e-4f

__device__ double g_loss_accum;
__device__ int    g_listcnt;
__device__ __align__(16) float g_enorm[KC];
__device__ __align__(16) float g_xn[M_ROWS];
__device__ __align__(16) int4  g_cand[M_ROWS];
__device__ __align__(16) int   g_list[M_ROWS];
// fp16 B fragments (e * 1024): [g=k32(8)][code(1024)][q(4)] x uint4
//  comp = (k16&1)*2 + h : { k16even(h0,h1), k16odd(h0,h1) }
//  h0 = fp16x2(k = 16*k16 + 2q, +1), h1 = fp16x2(k = 16*k16 + 8 + 2q, +1)
__device__ __align__(16) uint4 g_Bh[8 * 1024 * 4];

__device__ __forceinline__ void mma_fp16(float* c, const uint32_t* a, uint32_t b0, uint32_t b1) {
    asm volatile("mma.sync.aligned.m16n8k16.row.col.f32.f16.f16.f32 "
                 "{%0,%1,%2,%3}, {%4,%5,%6,%7}, {%8,%9}, {%0,%1,%2,%3};"
                 : "+f"(c[0]), "+f"(c[1]), "+f"(c[2]), "+f"(c[3])
                 : "r"(a[0]), "r"(a[1]), "r"(a[2]), "r"(a[3]), "r"(b0), "r"(b1));
}
// value-then-lowest-index comparator (reference tie-break)
__device__ __forceinline__ bool bt(float va, int ia, float vb, int ib) {
    return va < vb || (va == vb && ia < ib);
}

// ---------------------------------------------------------------------------
// Prep: e-norms (R2-verbatim reduction), fp16 B fragment images, zero accums.
// ---------------------------------------------------------------------------
__global__ void vq_prep(const float* __restrict__ E) {
    int code = blockIdx.x;
    int t = threadIdx.x;          // 64 threads, 4 elems each
    const float4* row = (const float4*)(E + (size_t)code * D);
    float4 v = row[t];
    float s = v.x * v.x + v.y * v.y + v.z * v.z + v.w * v.w;
    #pragma unroll
    for (int o = 16; o > 0; o >>= 1) s += __shfl_xor_sync(0xFFFFFFFFu, s, o);
    __shared__ float ws[2];
    if ((t & 31) == 0) ws[t >> 5] = s;
    __syncthreads();
    if (t == 0) {
        g_enorm[code] = ws[0] + ws[1];
        if (code == 0) { g_loss_accum = 0.0; g_listcnt = 0; }
    }

    // fp16 pairs (scaled x1024) into fragment image; thread t owns pairs 2t, 2t+1
    uint32_t* W = (uint32_t*)g_Bh;
    float f[4] = {v.x, v.y, v.z, v.w};
    #pragma unroll
    for (int pp = 0; pp < 2; pp++) {
        int p = 2 * t + pp;              // pair index (k = 2p, 2p+1)
        int k16 = p >> 3, r = p & 7, h = r >> 2, q = r & 3;
        int g = k16 >> 1, comp = (k16 & 1) * 2 + h;
        __half2 hv = __floats2half2_rn(f[pp * 2] * 1024.f, f[pp * 2 + 1] * 1024.f);
        W[(((size_t)g * 1024 + code) * 4 + q) * 4 + comp] = *(uint32_t*)&hv;
    }
}

// ---------------------------------------------------------------------------
// xnorm: R2's per-row ||x||^2, verbatim structure.
// ---------------------------------------------------------------------------
__global__ void vq_xnorm(const float* __restrict__ X) {
    int tid = threadIdx.x;
    int row0 = blockIdx.x * 128;
    int r = tid >> 1, h = tid & 1;
    const float4* xr = (const float4*)(X + (size_t)(row0 + r) * D + h * 128);
    float s = 0.f;
    #pragma unroll
    for (int j = 0; j < 32; j++) {
        float4 v = xr[j];
        s += v.x * v.x + v.y * v.y + v.z * v.z + v.w * v.w;
    }
    s += __shfl_xor_sync(0xFFFFFFFFu, s, 1);
    if (h == 0) g_xn[row0 + r] = s;
}

// ---------------------------------------------------------------------------
// Filter: fp16 m16n8k16 warp-MMA, fp16 A in smem (2 CTAs/SM), B frags via
// coalesced LDG.128 (one load feeds two MMAs). Top-3 per row + flag.
// ---------------------------------------------------------------------------
__global__ void __launch_bounds__(256, 2)
vq_filter(const float* __restrict__ X) {
    extern __shared__ char sm[];
    const int tid  = threadIdx.x;
    const int lane = tid & 31;
    const int warp = tid >> 5;
    const int row0 = blockIdx.x * 128;

    float*    s_en = (float*)(sm + FS_EN);
    uint32_t* Aw   = (uint32_t*)(sm + FS_A);

    // A tile -> fp16 smem (word stride 132)
    for (int i = tid; i < 128 * 64; i += 256) {
        int r = i >> 6, c4 = i & 63;
        float4 v = *(const float4*)(X + (size_t)(row0 + r) * D + c4 * 4);
        __half2 h0 = __floats2half2_rn(v.x, v.y);
        __half2 h1 = __floats2half2_rn(v.z, v.w);
        uint32_t* dst = Aw + r * AW_STRIDE + c4 * 2;
        dst[0] = *(uint32_t*)&h0;
        dst[1] = *(uint32_t*)&h1;
    }
    for (int i = tid; i < KC; i += 256) s_en[i] = g_enorm[i];
    __syncthreads();

    const int rA = warp * 16 + (lane >> 2);
    const int q  = lane & 3;
    const uint32_t* pA0 = Aw + rA * AW_STRIDE + q;            // + s*8 per k16
    const uint32_t* pA1 = pA0 + 8 * AW_STRIDE;

    float v1[2] = {3e38f, 3e38f}, v2[2] = {3e38f, 3e38f}, v3[2] = {3e38f, 3e38f};
    int   i1[2] = {0, 0},         i2[2] = {0, 0},         i3[2] = {0, 0};

    #define INS3(slot, sv, sidx) do { \
        float _s = (sv); int _i = (sidx); \
        if (_s < v3[slot]) { \
            if (_s < v2[slot]) { \
                v3[slot] = v2[slot]; i3[slot] = i2[slot]; \
                if (_s < v1[slot]) { v2[slot] = v1[slot]; i2[slot] = i1[slot]; \
                                     v1[slot] = _s; i1[slot] = _i; } \
                else               { v2[slot] = _s; i2[slot] = _i; } \
            } else { v3[slot] = _s; i3[slot] = _i; } \
        } } while (0)

    for (int nc = 0; nc < 8; nc++) {
        float C[16][4];
        #pragma unroll
        for (int nt = 0; nt < 16; nt++)
            #pragma unroll
            for (int j = 0; j < 4; j++) C[nt][j] = 0.f;

        #pragma unroll
        for (int g = 0; g < 8; g++) {
            // A frags for k16 steps s=2g (even) and s=2g+1 (odd)
            uint32_t aE[4], aO[4];
            int wE = 16 * g, wO = wE + 8;     // word offset s*8
            aE[0] = pA0[wE];     aE[1] = pA1[wE];
            aE[2] = pA0[wE + 4]; aE[3] = pA1[wE + 4];
            aO[0] = pA0[wO];     aO[1] = pA1[wO];
            aO[2] = pA0[wO + 4]; aO[3] = pA1[wO + 4];
            const uint4* pb = g_Bh + ((size_t)g * 1024 + nc * 128 + (lane >> 2)) * 4 + q;
            #pragma unroll
            for (int nt = 0; nt < 16; nt++) {
                uint4 b = __ldg(pb + nt * 32);
                mma_fp16(C[nt], aE, b.x, b.y);
                mma_fp16(C[nt], aO, b.z, b.w);
            }
        }

        // epilogue: approx score = en - 2*dot/1024 (xn-free ranking), top-3
        #pragma unroll
        for (int nt = 0; nt < 16; nt++) {
            int cl = nt * 8 + q * 2;
            int col0 = nc * 128 + cl;
            float en0 = s_en[col0], en1 = s_en[col0 + 1];
            INS3(0, __fmaf_rn(-0x1p-9f, C[nt][0], en0), col0);
            INS3(0, __fmaf_rn(-0x1p-9f, C[nt][1], en1), col0 + 1);
            INS3(1, __fmaf_rn(-0x1p-9f, C[nt][2], en0), col0);
            INS3(1, __fmaf_rn(-0x1p-9f, C[nt][3], en1), col0 + 1);
        }
    }

    // quad merge (lanes sharing rows)
    #pragma unroll
    for (int o = 1; o < 4; o <<= 1) {
        #pragma unroll
        for (int sl = 0; sl < 2; sl++) {
            float tv[3]; int ti[3];
            tv[0] = __shfl_xor_sync(0xFFFFFFFFu, v1[sl], o);
            ti[0] = __shfl_xor_sync(0xFFFFFFFFu, i1[sl], o);
            tv[1] = __shfl_xor_sync(0xFFFFFFFFu, v2[sl], o);
            ti[1] = __shfl_xor_sync(0xFFFFFFFFu, i2[sl], o);
            tv[2] = __shfl_xor_sync(0xFFFFFFFFu, v3[sl], o);
            ti[2] = __shfl_xor_sync(0xFFFFFFFFu, i3[sl], o);
            float mv[3] = {v1[sl], v2[sl], v3[sl]};
            int   mi[3] = {i1[sl], i2[sl], i3[sl]};
            float rv[3]; int ri[3];
            int a = 0, b = 0;
            #pragma unroll
            for (int k = 0; k < 3; k++) {
                bool ta = (b >= 3) || (a < 3 && bt(mv[a], mi[a], tv[b], ti[b]));
                rv[k] = ta ? mv[a] : tv[b];
                ri[k] = ta ? mi[a] : ti[b];
                if (ta) a++; else b++;
            }
            v1[sl] = rv[0]; i1[sl] = ri[0];
            v2[sl] = rv[1]; i2[sl] = ri[1];
            v3[sl] = rv[2]; i3[sl] = ri[2];
        }
    }

    if (q == 0) {
        int f0 = (v3[0] < v1[0] + WINF) ? 1 : 0;
        int f1 = (v3[1] < v1[1] + WINF) ? 1 : 0;
        g_cand[row0 + rA]     = make_int4(i1[0], i2[0], i3[0], f0);
        g_cand[row0 + rA + 8] = make_int4(i1[1], i2[1], i3[1], f1);
    }
}

// ---------------------------------------------------------------------------
// Refine: thread-per-candidate exact chains, double-buffered E prefetch.
// ---------------------------------------------------------------------------
#define RX_STRIDE 264
__global__ void __launch_bounds__(256, 3)
vq_refine(const float* __restrict__ X, const float* __restrict__ E,
          float* __restrict__ out) {
    extern __shared__ float sxr[];         // 64 rows x 264 floats
    __shared__ int   s_bi[64];
    __shared__ float s_lv[64];
    const int tid = threadIdx.x;
    const int r   = tid >> 2;              // row within block
    const int j   = tid & 3;               // candidate slot
    const int row0 = blockIdx.x * 64;
    const int row  = row0 + r;

    for (int i = tid; i < 64 * 64; i += 256) {
        int rr = i >> 6, c4 = i & 63;
        float4 v = *(const float4*)(X + (size_t)(row0 + rr) * D + c4 * 4);
        *(float4*)(sxr + rr * RX_STRIDE + c4 * 4) = v;
    }
    __syncthreads();

    const int4 cd = g_cand[row];
    float bv = 3e38f; int bn = 0x7FFFFFFF;

    if (cd.w) {
        if (j == 0) {
            int slot = atomicAdd(&g_listcnt, 1);
            g_list[slot] = row;
        }
    } else {
        const float xn = g_xn[row];
        int c = (j == 0) ? cd.x : (j == 1) ? cd.y : (j == 2) ? cd.z : cd.x;
        const float*  xr = sxr + r * RX_STRIDE;
        const float4* ee = (const float4*)(E + (size_t)c * D);
        float4 b0[4], b1[4];
        #pragma unroll
        for (int i = 0; i < 4; i++) b0[i] = __ldg(&ee[i]);
        float d = 0.f;
        #pragma unroll
        for (int t = 0; t < 16; t++) {
            float4* cur = (t & 1) ? b1 : b0;
            float4* nxt = (t & 1) ? b0 : b1;
            if (t < 15) {
                #pragma unroll
                for (int i = 0; i < 4; i++) nxt[i] = __ldg(&ee[(t + 1) * 4 + i]);
            }
            #pragma unroll
            for (int i = 0; i < 4; i++) {
                float4 xv = *(const float4*)(xr + t * 16 + i * 4);
                d = __fmaf_rn(xv.x, cur[i].x, d);
                d = __fmaf_rn(xv.y, cur[i].y, d);
                d = __fmaf_rn(xv.z, cur[i].z, d);
                d = __fmaf_rn(xv.w, cur[i].w, d);
            }
        }
        bv = __fmaf_rn(-2.f, d, __fadd_rn(xn, __ldg(&g_enorm[c])));
        bn = c;
    }

    // group-of-4 argmin (lowest-index ties)
    #pragma unroll
    for (int o = 1; o < 4; o <<= 1) {
        float ov = __shfl_xor_sync(0xFFFFFFFFu, bv, o);
        int   on = __shfl_xor_sync(0xFFFFFFFFu, bn, o);
        if (bt(ov, on, bv, bn)) { bv = ov; bn = on; }
    }
    if (j == 0) {
        s_bi[r] = cd.w ? -1 : bn;
        s_lv[r] = cd.w ? 0.f : bv;
    }
    __syncthreads();

    // loss partial
    if (tid < 64) {
        float l = s_lv[tid];
        #pragma unroll
        for (int o = 16; o > 0; o >>= 1) l += __shfl_xor_sync(0xFFFFFFFFu, l, o);
        if ((tid & 31) == 0) atomicAdd(&g_loss_accum, (double)l);
    }

    // STE output: out = fl(x + fl(q - x)); flagged rows handled by fullscan
    for (int u = tid; u < 64 * 64; u += 256) {
        int m = u >> 6, c4 = u & 63;
        int code = s_bi[m];
        if (code < 0) continue;
        float4 qv = __ldg((const float4*)(E + (size_t)code * D + c4 * 4));
        float4 x = *(const float4*)(sxr + m * RX_STRIDE + c4 * 4);
        float4 rr;
        rr.x = __fadd_rn(x.x, __fsub_rn(qv.x, x.x));
        rr.y = __fadd_rn(x.y, __fsub_rn(qv.y, x.y));
        rr.z = __fadd_rn(x.z, __fsub_rn(qv.z, x.z));
        rr.w = __fadd_rn(x.w, __fsub_rn(qv.w, x.w));
        *(float4*)(out + (size_t)(row0 + m) * D + c4 * 4) = rr;
    }
}

// ---------------------------------------------------------------------------
// Fullscan: 8 flagged rows per block, E reads shared across rows.
// ---------------------------------------------------------------------------
__global__ void __launch_bounds__(256)
vq_fullscan(const float* __restrict__ X, const float* __restrict__ E,
            float* __restrict__ out) {
    __shared__ float sx[8][260];
    __shared__ float s_xn8[8];
    __shared__ int   s_row[8];
    __shared__ float s_bv[8][8];   // [warp][rowslot]
    __shared__ int   s_bn[8][8];
    __shared__ int   s_code[8];
    const int tid  = threadIdx.x;
    const int lane = tid & 31;
    const int warp = tid >> 5;
    const int n = g_listcnt;
    const int groups = (n + 7) >> 3;

    for (int gi = blockIdx.x; gi < groups; gi += gridDim.x) {
        __syncthreads();
        if (tid < 8) {
            int idx = gi * 8 + tid;
            int row = (idx < n) ? g_list[idx] : -1;
            s_row[tid] = row;
            s_xn8[tid] = (row >= 0) ? g_xn[row] : 0.f;
        }
        __syncthreads();
        for (int u = tid; u < 8 * 64; u += 256) {
            int jj = u >> 6, c4 = u & 63;
            if (s_row[jj] >= 0)
                *(float4*)&sx[jj][c4 * 4] =
                    *(const float4*)(X + (size_t)s_row[jj] * D + c4 * 4);
        }
        __syncthreads();

        float dacc[4][8];
        #pragma unroll
        for (int qq = 0; qq < 4; qq++)
            #pragma unroll
            for (int jj = 0; jj < 8; jj++) dacc[qq][jj] = 0.f;

        const float4* e0 = (const float4*)(E + (size_t)(tid)       * D);
        const float4* e1 = (const float4*)(E + (size_t)(tid + 256) * D);
        const float4* e2 = (const float4*)(E + (size_t)(tid + 512) * D);
        const float4* e3 = (const float4*)(E + (size_t)(tid + 768) * D);
        #pragma unroll 4
        for (int k4 = 0; k4 < 64; k4++) {
            float4 ev0 = __ldg(&e0[k4]);
            float4 ev1 = __ldg(&e1[k4]);
            float4 ev2 = __ldg(&e2[k4]);
            float4 ev3 = __ldg(&e3[k4]);
            #pragma unroll
            for (int jj = 0; jj < 8; jj++) {
                float4 xv = *(const float4*)&sx[jj][k4 * 4];
                dacc[0][jj] = __fmaf_rn(xv.x, ev0.x, dacc[0][jj]);
                dacc[0][jj] = __fmaf_rn(xv.y, ev0.y, dacc[0][jj]);
                dacc[0][jj] = __fmaf_rn(xv.z, ev0.z, dacc[0][jj]);
                dacc[0][jj] = __fmaf_rn(xv.w, ev0.w, dacc[0][jj]);
                dacc[1][jj] = __fmaf_rn(xv.x, ev1.x, dacc[1][jj]);
                dacc[1][jj] = __fmaf_rn(xv.y, ev1.y, dacc[1][jj]);
                dacc[1][jj] = __fmaf_rn(xv.z, ev1.z, dacc[1][jj]);
                dacc[1][jj] = __fmaf_rn(xv.w, ev1.w, dacc[1][jj]);
                dacc[2][jj] = __fmaf_rn(xv.x, ev2.x, dacc[2][jj]);
                dacc[2][jj] = __fmaf_rn(xv.y, ev2.y, dacc[2][jj]);
                dacc[2][jj] = __fmaf_rn(xv.z, ev2.z, dacc[2][jj]);
                dacc[2][jj] = __fmaf_rn(xv.w, ev2.w, dacc[2][jj]);
                dacc[3][jj] = __fmaf_rn(xv.x, ev3.x, dacc[3][jj]);
                dacc[3][jj] = __fmaf_rn(xv.y, ev3.y, dacc[3][jj]);
                dacc[3][jj] = __fmaf_rn(xv.z, ev3.z, dacc[3][jj]);
                dacc[3][jj] = __fmaf_rn(xv.w, ev3.w, dacc[3][jj]);
            }
        }

        // per-row reductions
        #pragma unroll
        for (int jj = 0; jj < 8; jj++) {
            float xn = s_xn8[jj];
            float bv; int bn;
            float s = __fmaf_rn(-2.f, dacc[0][jj], __fadd_rn(xn, __ldg(&g_enorm[tid])));
            bv = s; bn = tid;
            s = __fmaf_rn(-2.f, dacc[1][jj], __fadd_rn(xn, __ldg(&g_enorm[tid + 256])));
            if (bt(s, tid + 256, bv, bn)) { bv = s; bn = tid + 256; }
            s = __fmaf_rn(-2.f, dacc[2][jj], __fadd_rn(xn, __ldg(&g_enorm[tid + 512])));
            if (bt(s, tid + 512, bv, bn)) { bv = s; bn = tid + 512; }
            s = __fmaf_rn(-2.f, dacc[3][jj], __fadd_rn(xn, __ldg(&g_enorm[tid + 768])));
            if (bt(s, tid + 768, bv, bn)) { bv = s; bn = tid + 768; }
            #pragma unroll
            for (int o = 16; o > 0; o >>= 1) {
                float ov = __shfl_xor_sync(0xFFFFFFFFu, bv, o);
                int   on = __shfl_xor_sync(0xFFFFFFFFu, bn, o);
                if (bt(ov, on, bv, bn)) { bv = ov; bn = on; }
            }
            if (lane == 0) { s_bv[warp][jj] = bv; s_bn[warp][jj] = bn; }
        }
        __syncthreads();
        if (tid < 8) {
            float fv = s_bv[0][tid]; int fn = s_bn[0][tid];
            #pragma unroll
            for (int w = 1; w < 8; w++)
                if (bt(s_bv[w][tid], s_bn[w][tid], fv, fn)) {
                    fv = s_bv[w][tid]; fn = s_bn[w][tid];
                }
            s_code[tid] = fn;
            if (s_row[tid] >= 0) atomicAdd(&g_loss_accum, (double)fv);
        }
        __syncthreads();

        #pragma unroll
        for (int jj = 0; jj < 8; jj++) {
            int row = s_row[jj];
            if (row < 0) continue;
            float qv = __ldg(&E[(size_t)s_code[jj] * D + tid]);
            float x  = sx[jj][tid];
            out[(size_t)row * D + tid] = __fadd_rn(x, __fsub_rn(qv, x));
        }
    }
}

__global__ void vq_finish(float* __restrict__ out, int total_elems) {
    out[total_elems] = (float)(1.25 * g_loss_accum / (double)total_elems);
}

extern "C" void kernel_launch(void* const* d_in, const int* in_sizes, int n_in,
                              void* d_out, int out_size) {
    const float* X = (const float*)d_in[0];   // latents  [8192, 2048] fp32
    const float* E = (const float*)d_in[1];   // embedding [1024, 256] fp32
    float* out = (float*)d_out;
    int M = in_sizes[0] / D;                  // 65536 rows

    cudaFuncSetAttribute(vq_filter, cudaFuncAttributeMaxDynamicSharedMemorySize, FS_TOTAL);
    cudaFuncSetAttribute(vq_refine, cudaFuncAttributeMaxDynamicSharedMemorySize,
                         64 * RX_STRIDE * 4);
    vq_prep<<<KC, 64>>>(E);
    vq_xnorm<<<M / 128, 256>>>(X);
    vq_filter<<<M / 128, 256, FS_TOTAL>>>(X);
    vq_refine<<<M / 64, 256, 64 * RX_STRIDE * 4>>>(X, E, out);
    vq_fullscan<<<256, 256>>>(X, E, out);
    vq_finish<<<1, 1>>>(out, out_size - 1);
}